// round 6
// baseline (speedup 1.0000x reference)
#include <cuda_runtime.h>
#include <cuda_bf16.h>
#include <math.h>
#include <stdint.h>

// ---------------------------------------------------------------------------
// EdgeMLPMPN via mma.sync bf16x3-split (hi*hi + hi*lo + lo*hi, fp32 acc).
// R6: unified 12-chunk (32-k) W stream, 2-deep cp.async double-buffer so
// staging overlaps compute. EPT=64, 2 CTAs/SM, 8 warps (4m x 2n).
// ---------------------------------------------------------------------------

#define EPT 64
#define THREADS 256
#define SA1 528   // A1 row stride bytes (256 bf16 + pad)
#define SA2 272   // h1 row stride (128 bf16 + pad)
#define SWS 80    // W chunk row stride (32 bf16 + 16B pad); 80*i%128 all-distinct

#define SM_A_HI 0
#define SM_A_LO 33792                   // 64*528
#define SM_W    67584                   // 2 bufs x (hi 10240 | lo 10240)
#define WBUF_STRIDE 20480
#define WLO_OFF 10240
#define SM_CTRL (SM_W + 40960)          // 108544
#define SM_SIDS (SM_CTRL)
#define SM_B1   (SM_CTRL + 512)
#define SM_B2   (SM_B1 + 512)
#define SM_W3   (SM_B2 + 512)
#define SM_R0   (SM_W3 + 512)
#define SM_R1   (SM_R0 + 256)
#define SMEM_BYTES (SM_R1 + 256)        // ~110.8KB -> 2 CTAs/SM

__device__ __align__(16) __nv_bfloat16 g_w1t_hi[128 * 256];
__device__ __align__(16) __nv_bfloat16 g_w1t_lo[128 * 256];
__device__ __align__(16) __nv_bfloat16 g_w2t_hi[128 * 128];
__device__ __align__(16) __nv_bfloat16 g_w2t_lo[128 * 128];

__device__ __forceinline__ uint32_t smem_u32(const void* p) {
    uint32_t a;
    asm("{ .reg .u64 t; cvta.to.shared.u64 t, %1; cvt.u32.u64 %0, t; }" : "=r"(a) : "l"(p));
    return a;
}
__device__ __forceinline__ void ldm_x4(uint32_t addr, uint32_t r[4]) {
    asm volatile("ldmatrix.sync.aligned.m8n8.x4.shared.b16 {%0,%1,%2,%3}, [%4];"
                 : "=r"(r[0]), "=r"(r[1]), "=r"(r[2]), "=r"(r[3]) : "r"(addr));
}
__device__ __forceinline__ void hmma(float c[4], const uint32_t a[4],
                                     uint32_t b0, uint32_t b1) {
    asm volatile(
        "mma.sync.aligned.m16n8k16.row.col.f32.bf16.bf16.f32 "
        "{%0,%1,%2,%3}, {%4,%5,%6,%7}, {%8,%9}, {%0,%1,%2,%3};"
        : "+f"(c[0]), "+f"(c[1]), "+f"(c[2]), "+f"(c[3])
        : "r"(a[0]), "r"(a[1]), "r"(a[2]), "r"(a[3]), "r"(b0), "r"(b1));
}
__device__ __forceinline__ void cp16(uint32_t dst, const void* src) {
    asm volatile("cp.async.cg.shared.global [%0], [%1], 16;" :: "r"(dst), "l"(src));
}
__device__ __forceinline__ void cp_commit() {
    asm volatile("cp.async.commit_group;" ::: "memory");
}
__device__ __forceinline__ void cp_wait1() {
    asm volatile("cp.async.wait_group 1;" ::: "memory");
}
__device__ __forceinline__ float elu1(float v) { return v > 0.0f ? v : expm1f(v); }
__device__ __forceinline__ void split_bf16(float v, __nv_bfloat16& hi, __nv_bfloat16& lo) {
    hi = __float2bfloat16_rn(v);
    lo = __float2bfloat16_rn(v - __bfloat162float(hi));
}
union BF4 { __nv_bfloat16 b[4]; unsigned long long u; };
union BF2 { __nv_bfloat16 b[2]; uint32_t u; };

// ---------------- prologue: transpose + bf16-split W1, W2 ----------------
__global__ void wconv_kernel(const float* __restrict__ W1, const float* __restrict__ W2) {
    int i = blockIdx.x * blockDim.x + threadIdx.x;
    if (i < 32768) {
        int n = i >> 8, k = i & 255;
        float v = __ldg(W1 + k * 128 + n);
        __nv_bfloat16 h, l; split_bf16(v, h, l);
        g_w1t_hi[i] = h; g_w1t_lo[i] = l;
    } else if (i < 49152) {
        int j = i - 32768;
        int n = j >> 7, k = j & 127;
        float v = __ldg(W2 + k * 128 + n);
        __nv_bfloat16 h, l; split_bf16(v, h, l);
        g_w2t_hi[j] = h; g_w2t_lo[j] = l;
    }
}

// stage unified chunk c (0..7: W1, 8..11: W2) into buf (c&1); 1 commit group
__device__ __forceinline__ void stage_chunk(uint32_t sb, int c, int tid) {
    const __nv_bfloat16* gh;
    const __nv_bfloat16* gl;
    int row_elems, col0;
    if (c < 8) { gh = g_w1t_hi; gl = g_w1t_lo; row_elems = 256; col0 = c * 32; }
    else       { gh = g_w2t_hi; gl = g_w2t_lo; row_elems = 128; col0 = (c - 8) * 32; }
    uint32_t base = sb + SM_W + (uint32_t)(c & 1) * WBUF_STRIDE;
#pragma unroll
    for (int it = 0; it < 2; it++) {
        int idx = tid + it * THREADS;      // 0..511
        int n = idx >> 2, j = idx & 3;     // 4 x 16B per 64B row
        const __nv_bfloat16* src = gh + n * row_elems + col0 + j * 8;
        cp16(base + n * SWS + j * 16, src);
        cp16(base + WLO_OFF + n * SWS + j * 16, gl + n * row_elems + col0 + j * 8);
    }
    cp_commit();
}

// compute one 32-k chunk (2 k-tiles) of the 3-pass split GEMM
__device__ __forceinline__ void gemm_chunk(uint32_t sb, int buf, int sa, int a_k0byte,
                                           int e0, int n0, int lane,
                                           float acc[8][4]) {
    const int rowA = lane & 15;
    const int chA = (lane >> 4) * 16;
    const int rowB = (lane & 7) + ((lane >> 4) << 3);
    const int chB = ((lane >> 3) & 1) * 16;

    uint32_t aH = sb + SM_A_HI + (e0 + rowA) * sa + chA + a_k0byte;
    uint32_t aL = sb + SM_A_LO + (e0 + rowA) * sa + chA + a_k0byte;
    uint32_t wb = sb + SM_W + (uint32_t)buf * WBUF_STRIDE;
    uint32_t bH = wb + (n0 + rowB) * SWS + chB;
    uint32_t bL = bH + WLO_OFF;

#pragma unroll
    for (int kt = 0; kt < 2; kt++) {
        uint32_t ah[4], al[4];
        ldm_x4(aH + kt * 32, ah);
        ldm_x4(aL + kt * 32, al);
#pragma unroll
        for (int ntp = 0; ntp < 4; ntp++) {
            uint32_t bh[4], bl[4];
            ldm_x4(bH + ntp * 16 * SWS + kt * 32, bh);
            ldm_x4(bL + ntp * 16 * SWS + kt * 32, bl);
            hmma(acc[2 * ntp + 0], ah, bh[0], bh[1]);
            hmma(acc[2 * ntp + 1], ah, bh[2], bh[3]);
            hmma(acc[2 * ntp + 0], ah, bl[0], bl[1]);
            hmma(acc[2 * ntp + 1], ah, bl[2], bl[3]);
            hmma(acc[2 * ntp + 0], al, bh[0], bh[1]);
            hmma(acc[2 * ntp + 1], al, bh[2], bh[3]);
        }
    }
}

__global__ void __launch_bounds__(THREADS, 2)
edge_mlp_hmma_kernel(const float* __restrict__ x, const void* __restrict__ ei,
                     const float* __restrict__ b1, const float* __restrict__ b2,
                     const float* __restrict__ W3, const float* __restrict__ b3,
                     float* __restrict__ out, int n_edges, int n_nodes) {
    extern __shared__ char smem[];
    const uint32_t sb = smem_u32(smem);
    const int tid = threadIdx.x, wid = tid >> 5, lane = tid & 31;
    const int gid = lane >> 2, tig = lane & 3;
    const int mw = wid >> 1, nw = wid & 1;
    const int e0 = mw * 16, n0 = nw * 64;
    const int tile = blockIdx.x * EPT;
    const int nv = min(EPT, n_edges - tile);

    // sniff edge_index dtype (int64 LE values < 2^31 => odd 32-bit words all 0)
    const int* ei32 = (const int*)ei;
    const long long* ei64 = (const long long*)ei;
    int odd_or = 0;
#pragma unroll
    for (int i = 1; i < 64; i += 2) odd_or |= ei32[i];
    const bool is64 = (odd_or == 0);

    int* sids = (int*)(smem + SM_SIDS);
    float* b1s = (float*)(smem + SM_B1);
    float* b2s = (float*)(smem + SM_B2);
    float* w3s = (float*)(smem + SM_W3);
    if (tid < 128) {
        int half = tid >> 6, e = tid & 63;
        int ec = e < nv ? e : (nv - 1);
        int pos = half * n_edges + tile + ec;
        long long node = is64 ? ei64[pos] : (long long)ei32[pos];
        node = node < 0 ? 0 : (node >= n_nodes ? (long long)n_nodes - 1 : node);
        sids[tid] = (int)node;
        b1s[tid] = __ldg(b1 + tid);
        b2s[tid] = __ldg(b2 + tid);
        w3s[tid] = __ldg(W3 + tid);
    }
    __syncthreads();

    // pipeline prologue: chunks 0,1 in flight; overlap with gather
    stage_chunk(sb, 0, tid);
    stage_chunk(sb, 1, tid);

    // ---- gather + split: A1 [64 e][256 k] bf16 hi/lo ----
    const float4* x4 = reinterpret_cast<const float4*>(x);
#pragma unroll 4
    for (int it = 0; it < 16; it++) {
        int idx = tid + it * THREADS;
        int e = idx >> 6, q = idx & 63;
        int half = q >> 5, kq = q & 31;
        int node = sids[half * 64 + e];
        float4 v = __ldg(x4 + node * 32 + kq);
        int k = q * 4;
        BF4 h, l;
        split_bf16(v.x, h.b[0], l.b[0]);
        split_bf16(v.y, h.b[1], l.b[1]);
        split_bf16(v.z, h.b[2], l.b[2]);
        split_bf16(v.w, h.b[3], l.b[3]);
        *reinterpret_cast<unsigned long long*>(smem + SM_A_HI + e * SA1 + k * 2) = h.u;
        *reinterpret_cast<unsigned long long*>(smem + SM_A_LO + e * SA1 + k * 2) = l.u;
    }

    float acc[8][4];
#pragma unroll
    for (int j = 0; j < 8; j++)
#pragma unroll
        for (int q = 0; q < 4; q++) acc[j][q] = 0.0f;

    // ---- unified pipelined chunk loop: 0..7 = layer1, 8..11 = layer2 ----
#pragma unroll 1
    for (int c = 0; c < 12; c++) {
        cp_wait1();            // buf[c&1] (chunk c) resident
        __syncthreads();       // also covers gather completion at c==0

        if (c < 8) {
            gemm_chunk(sb, c & 1, SA1, c * 64, e0, n0, lane, acc);
        } else {
            gemm_chunk(sb, c & 1, SA2, (c - 8) * 64, e0, n0, lane, acc);
        }

        // ---- epilogue 1 between the two layers (after chunk 7 computed) ----
        if (c == 7) {
            // chunks 8,9 already staged (issued at c=6,7) - do NOT overwrite yet.
            // Resplit h1 into A region; A1 reads are done by all warps after this sync:
            __syncthreads();
#pragma unroll
            for (int nt = 0; nt < 8; nt++) {
                int nc = n0 + 8 * nt + 2 * tig;
                int ea = e0 + gid, eb = ea + 8;
                float v00 = elu1(acc[nt][0] + b1s[nc]);
                float v01 = elu1(acc[nt][1] + b1s[nc + 1]);
                float v10 = elu1(acc[nt][2] + b1s[nc]);
                float v11 = elu1(acc[nt][3] + b1s[nc + 1]);
                BF2 h, l;
                split_bf16(v00, h.b[0], l.b[0]);
                split_bf16(v01, h.b[1], l.b[1]);
                *reinterpret_cast<uint32_t*>(smem + SM_A_HI + ea * SA2 + nc * 2) = h.u;
                *reinterpret_cast<uint32_t*>(smem + SM_A_LO + ea * SA2 + nc * 2) = l.u;
                split_bf16(v10, h.b[0], l.b[0]);
                split_bf16(v11, h.b[1], l.b[1]);
                *reinterpret_cast<uint32_t*>(smem + SM_A_HI + eb * SA2 + nc * 2) = h.u;
                *reinterpret_cast<uint32_t*>(smem + SM_A_LO + eb * SA2 + nc * 2) = l.u;
            }
#pragma unroll
            for (int j = 0; j < 8; j++)
#pragma unroll
                for (int q = 0; q < 4; q++) acc[j][q] = 0.0f;
        }

        __syncthreads();       // all warps done reading buf[c&1] / h1 written
        if (c + 2 < 12) stage_chunk(sb, c + 2, tid);
    }

    // ---- epilogue 2: bias + elu + dot(W3), butterfly over tig ----
    float pa = 0.0f, pb = 0.0f;
#pragma unroll
    for (int nt = 0; nt < 8; nt++) {
        int nc = n0 + 8 * nt + 2 * tig;
        float w0 = w3s[nc], w1 = w3s[nc + 1];
        pa += elu1(acc[nt][0] + b2s[nc]) * w0 + elu1(acc[nt][1] + b2s[nc + 1]) * w1;
        pb += elu1(acc[nt][2] + b2s[nc]) * w0 + elu1(acc[nt][3] + b2s[nc + 1]) * w1;
    }
    pa += __shfl_xor_sync(0xffffffff, pa, 1);
    pa += __shfl_xor_sync(0xffffffff, pa, 2);
    pb += __shfl_xor_sync(0xffffffff, pb, 1);
    pb += __shfl_xor_sync(0xffffffff, pb, 2);
    float* red = (float*)(smem + (nw ? SM_R1 : SM_R0));
    if (tig == 0) {
        red[e0 + gid] = pa;
        red[e0 + gid + 8] = pb;
    }
    __syncthreads();
    if (tid < 64 && tid < nv) {
        float* r0 = (float*)(smem + SM_R0);
        float* r1 = (float*)(smem + SM_R1);
        out[tile + tid] = r0[tid] + r1[tid] + __ldg(b3);
    }
}

extern "C" void kernel_launch(void* const* d_in, const int* in_sizes, int n_in,
                              void* d_out, int out_size) {
    const float* x  = (const float*)d_in[0];
    const void*  ei = d_in[1];
    const float* W1 = (const float*)d_in[2];
    const float* b1 = (const float*)d_in[3];
    const float* W2 = (const float*)d_in[4];
    const float* b2 = (const float*)d_in[5];
    const float* W3 = (const float*)d_in[6];
    const float* b3 = (const float*)d_in[7];
    float* out = (float*)d_out;

    const int n_edges = out_size;
    const int n_nodes = in_sizes[0] / 128;

    cudaFuncSetAttribute(edge_mlp_hmma_kernel,
                         cudaFuncAttributeMaxDynamicSharedMemorySize, SMEM_BYTES);

    wconv_kernel<<<192, 256>>>(W1, W2);
    const int grid = (n_edges + EPT - 1) / EPT;
    edge_mlp_hmma_kernel<<<grid, THREADS, SMEM_BYTES>>>(x, ei, b1, b2, W3, b3,
                                                        out, n_edges, n_nodes);
}

// round 7
// speedup vs baseline: 1.0663x; 1.0663x over previous
#include <cuda_runtime.h>
#include <cuda_bf16.h>
#include <math.h>
#include <stdint.h>

// ---------------------------------------------------------------------------
// EdgeMLPMPN via mma.sync bf16x3-split (hi*hi + hi*lo + lo*hi, fp32 acc).
// R7 = R5 skeleton (EPT=64, 2 CTAs/SM, 64k W stages, cp.async W prefetch)
// with the inner HMMA schedule reordered pass-major so same-accumulator
// HMMAs are 4 apart (was 1 apart -> RAW-stall on tensor latency).
// ---------------------------------------------------------------------------

#define EPT 64
#define THREADS 256
#define SA1 528   // A1 row stride bytes (256 bf16 + pad); ldmatrix conflict-free
#define SA2 272   // h1 row stride (128 bf16 + pad)
#define SWS 144   // W chunk row stride (64 bf16 + pad)

#define SM_A_HI 0
#define SM_A_LO 33792                  // 64*528
#define SM_W_HI 67584
#define SM_W_LO (SM_W_HI + 18432)      // 128*144
#define SM_CTRL (SM_W_LO + 18432)      // 104448
#define SM_SIDS (SM_CTRL)              // 128 ints
#define SM_B1   (SM_CTRL + 512)
#define SM_B2   (SM_B1 + 512)
#define SM_W3   (SM_B2 + 512)
#define SM_R0   (SM_W3 + 512)
#define SM_R1   (SM_R0 + 256)
#define SMEM_BYTES (SM_R1 + 256)       // 104.5KB -> 2 CTAs/SM

__device__ __align__(16) __nv_bfloat16 g_w1t_hi[128 * 256];
__device__ __align__(16) __nv_bfloat16 g_w1t_lo[128 * 256];
__device__ __align__(16) __nv_bfloat16 g_w2t_hi[128 * 128];
__device__ __align__(16) __nv_bfloat16 g_w2t_lo[128 * 128];

__device__ __forceinline__ uint32_t smem_u32(const void* p) {
    uint32_t a;
    asm("{ .reg .u64 t; cvta.to.shared.u64 t, %1; cvt.u32.u64 %0, t; }" : "=r"(a) : "l"(p));
    return a;
}
__device__ __forceinline__ void ldm_x4(uint32_t addr, uint32_t r[4]) {
    asm volatile("ldmatrix.sync.aligned.m8n8.x4.shared.b16 {%0,%1,%2,%3}, [%4];"
                 : "=r"(r[0]), "=r"(r[1]), "=r"(r[2]), "=r"(r[3]) : "r"(addr));
}
__device__ __forceinline__ void hmma(float c[4], const uint32_t a[4],
                                     uint32_t b0, uint32_t b1) {
    asm volatile(
        "mma.sync.aligned.m16n8k16.row.col.f32.bf16.bf16.f32 "
        "{%0,%1,%2,%3}, {%4,%5,%6,%7}, {%8,%9}, {%0,%1,%2,%3};"
        : "+f"(c[0]), "+f"(c[1]), "+f"(c[2]), "+f"(c[3])
        : "r"(a[0]), "r"(a[1]), "r"(a[2]), "r"(a[3]), "r"(b0), "r"(b1));
}
__device__ __forceinline__ void cp16(uint32_t dst, const void* src) {
    asm volatile("cp.async.cg.shared.global [%0], [%1], 16;" :: "r"(dst), "l"(src));
}
__device__ __forceinline__ void cp_commit() {
    asm volatile("cp.async.commit_group;" ::: "memory");
}
__device__ __forceinline__ void cp_wait0() {
    asm volatile("cp.async.wait_group 0;" ::: "memory");
}
__device__ __forceinline__ float elu1(float v) { return v > 0.0f ? v : expm1f(v); }
__device__ __forceinline__ void split_bf16(float v, __nv_bfloat16& hi, __nv_bfloat16& lo) {
    hi = __float2bfloat16_rn(v);
    lo = __float2bfloat16_rn(v - __bfloat162float(hi));
}
union BF4 { __nv_bfloat16 b[4]; unsigned long long u; };
union BF2 { __nv_bfloat16 b[2]; uint32_t u; };

// ---------------- prologue: transpose + bf16-split W1, W2 ----------------
__global__ void wconv_kernel(const float* __restrict__ W1, const float* __restrict__ W2) {
    int i = blockIdx.x * blockDim.x + threadIdx.x;
    if (i < 32768) {                     // W1T[n][k] <- W1[k][n]
        int n = i >> 8, k = i & 255;
        float v = __ldg(W1 + k * 128 + n);
        __nv_bfloat16 h, l; split_bf16(v, h, l);
        g_w1t_hi[i] = h; g_w1t_lo[i] = l;
    } else if (i < 49152) {              // W2T[n][k] <- W2[k][n]
        int j = i - 32768;
        int n = j >> 7, k = j & 127;
        float v = __ldg(W2 + k * 128 + n);
        __nv_bfloat16 h, l; split_bf16(v, h, l);
        g_w2t_hi[j] = h; g_w2t_lo[j] = l;
    }
}

// async-stage one [128 n][64 k] hi/lo W chunk
__device__ __forceinline__ void stage_w_async(uint32_t sb,
                                              const __nv_bfloat16* __restrict__ gh,
                                              const __nv_bfloat16* __restrict__ gl,
                                              int row_elems, int col0, int tid) {
#pragma unroll
    for (int it = 0; it < 4; it++) {
        int idx = tid + it * THREADS;
        int n = idx >> 3, j = idx & 7;
        cp16(sb + SM_W_HI + n * SWS + j * 16, gh + n * row_elems + col0 + j * 8);
        cp16(sb + SM_W_LO + n * SWS + j * 16, gl + n * row_elems + col0 + j * 8);
    }
    cp_commit();
}

// one 64-k stage (4 k-tiles); pass-major HMMA schedule over n-tile pairs
__device__ __forceinline__ void gemm_stage(uint32_t sb, int sa, int a_k0byte,
                                           int e0, int n0, int lane,
                                           float acc[8][4]) {
    const int rowA = lane & 15;
    const int chA = (lane >> 4) * 16;
    const int rowB = (lane & 7) + ((lane >> 4) << 3);
    const int chB = ((lane >> 3) & 1) * 16;

    uint32_t aH = sb + SM_A_HI + (e0 + rowA) * sa + chA + a_k0byte;
    uint32_t aL = sb + SM_A_LO + (e0 + rowA) * sa + chA + a_k0byte;
    uint32_t bH = sb + SM_W_HI + (n0 + rowB) * SWS + chB;
    uint32_t bL = sb + SM_W_LO + (n0 + rowB) * SWS + chB;

#pragma unroll
    for (int kt = 0; kt < 4; kt++) {
        uint32_t ah[4], al[4];
        ldm_x4(aH + kt * 32, ah);
        ldm_x4(aL + kt * 32, al);
#pragma unroll
        for (int g = 0; g < 2; g++) {           // n-tile pair (ntp = 2g, 2g+1)
            uint32_t bh0[4], bh1[4], bl0[4], bl1[4];
            ldm_x4(bH + (2 * g + 0) * 16 * SWS + kt * 32, bh0);
            ldm_x4(bH + (2 * g + 1) * 16 * SWS + kt * 32, bh1);
            ldm_x4(bL + (2 * g + 0) * 16 * SWS + kt * 32, bl0);
            ldm_x4(bL + (2 * g + 1) * 16 * SWS + kt * 32, bl1);
            float (*a4)[4] = &acc[4 * g];
            // pass hh
            hmma(a4[0], ah, bh0[0], bh0[1]);
            hmma(a4[1], ah, bh0[2], bh0[3]);
            hmma(a4[2], ah, bh1[0], bh1[1]);
            hmma(a4[3], ah, bh1[2], bh1[3]);
            // pass hl
            hmma(a4[0], ah, bl0[0], bl0[1]);
            hmma(a4[1], ah, bl0[2], bl0[3]);
            hmma(a4[2], ah, bl1[0], bl1[1]);
            hmma(a4[3], ah, bl1[2], bl1[3]);
            // pass lh
            hmma(a4[0], al, bh0[0], bh0[1]);
            hmma(a4[1], al, bh0[2], bh0[3]);
            hmma(a4[2], al, bh1[0], bh1[1]);
            hmma(a4[3], al, bh1[2], bh1[3]);
        }
    }
}

__global__ void __launch_bounds__(THREADS, 2)
edge_mlp_hmma_kernel(const float* __restrict__ x, const void* __restrict__ ei,
                     const float* __restrict__ b1, const float* __restrict__ b2,
                     const float* __restrict__ W3, const float* __restrict__ b3,
                     float* __restrict__ out, int n_edges, int n_nodes) {
    extern __shared__ char smem[];
    const uint32_t sb = smem_u32(smem);
    const int tid = threadIdx.x, wid = tid >> 5, lane = tid & 31;
    const int gid = lane >> 2, tig = lane & 3;
    const int mw = wid >> 1, nw = wid & 1;
    const int e0 = mw * 16, n0 = nw * 64;
    const int tile = blockIdx.x * EPT;
    const int nv = min(EPT, n_edges - tile);

    // sniff edge_index dtype (int64 LE values < 2^31 => odd 32-bit words all 0)
    const int* ei32 = (const int*)ei;
    const long long* ei64 = (const long long*)ei;
    int odd_or = 0;
#pragma unroll
    for (int i = 1; i < 64; i += 2) odd_or |= ei32[i];
    const bool is64 = (odd_or == 0);

    int* sids = (int*)(smem + SM_SIDS);
    float* b1s = (float*)(smem + SM_B1);
    float* b2s = (float*)(smem + SM_B2);
    float* w3s = (float*)(smem + SM_W3);
    if (tid < 128) {
        int half = tid >> 6, e = tid & 63;
        int ec = e < nv ? e : (nv - 1);
        int pos = half * n_edges + tile + ec;
        long long node = is64 ? ei64[pos] : (long long)ei32[pos];
        node = node < 0 ? 0 : (node >= n_nodes ? (long long)n_nodes - 1 : node);
        sids[tid] = (int)node;
        b1s[tid] = __ldg(b1 + tid);
        b2s[tid] = __ldg(b2 + tid);
        w3s[tid] = __ldg(W3 + tid);
    }
    __syncthreads();

    // prefetch W1 chunk 0 while gathering A
    stage_w_async(sb, g_w1t_hi, g_w1t_lo, 256, 0, tid);

    // ---- gather + split: A1 [64 e][256 k] bf16 hi/lo ----
    const float4* x4 = reinterpret_cast<const float4*>(x);
#pragma unroll 4
    for (int it = 0; it < 16; it++) {
        int idx = tid + it * THREADS;
        int e = idx >> 6, q = idx & 63;
        int half = q >> 5, kq = q & 31;
        int node = sids[half * 64 + e];
        float4 v = __ldg(x4 + node * 32 + kq);
        int k = q * 4;
        BF4 h, l;
        split_bf16(v.x, h.b[0], l.b[0]);
        split_bf16(v.y, h.b[1], l.b[1]);
        split_bf16(v.z, h.b[2], l.b[2]);
        split_bf16(v.w, h.b[3], l.b[3]);
        *reinterpret_cast<unsigned long long*>(smem + SM_A_HI + e * SA1 + k * 2) = h.u;
        *reinterpret_cast<unsigned long long*>(smem + SM_A_LO + e * SA1 + k * 2) = l.u;
    }
    cp_wait0();
    __syncthreads();

    float acc[8][4];
#pragma unroll
    for (int j = 0; j < 8; j++)
#pragma unroll
        for (int q = 0; q < 4; q++) acc[j][q] = 0.0f;

    // ---- layer 1: four 64-k stages ----
#pragma unroll 1
    for (int c = 0; c < 4; c++) {
        gemm_stage(sb, SA1, c * 128, e0, n0, lane, acc);
        __syncthreads();
        if (c < 3) {
            stage_w_async(sb, g_w1t_hi, g_w1t_lo, 256, (c + 1) * 64, tid);
            cp_wait0();
            __syncthreads();
        }
    }

    // prefetch W2 chunk 0; overlap with epilogue-1 resplit
    stage_w_async(sb, g_w2t_hi, g_w2t_lo, 128, 0, tid);

    // ---- epilogue 1: bias + elu, re-split h1 into A region (stride SA2) ----
#pragma unroll
    for (int nt = 0; nt < 8; nt++) {
        int nc = n0 + 8 * nt + 2 * tig;
        int ea = e0 + gid, eb = ea + 8;
        float v00 = elu1(acc[nt][0] + b1s[nc]);
        float v01 = elu1(acc[nt][1] + b1s[nc + 1]);
        float v10 = elu1(acc[nt][2] + b1s[nc]);
        float v11 = elu1(acc[nt][3] + b1s[nc + 1]);
        BF2 h, l;
        split_bf16(v00, h.b[0], l.b[0]);
        split_bf16(v01, h.b[1], l.b[1]);
        *reinterpret_cast<uint32_t*>(smem + SM_A_HI + ea * SA2 + nc * 2) = h.u;
        *reinterpret_cast<uint32_t*>(smem + SM_A_LO + ea * SA2 + nc * 2) = l.u;
        split_bf16(v10, h.b[0], l.b[0]);
        split_bf16(v11, h.b[1], l.b[1]);
        *reinterpret_cast<uint32_t*>(smem + SM_A_HI + eb * SA2 + nc * 2) = h.u;
        *reinterpret_cast<uint32_t*>(smem + SM_A_LO + eb * SA2 + nc * 2) = l.u;
    }
#pragma unroll
    for (int j = 0; j < 8; j++)
#pragma unroll
        for (int q = 0; q < 4; q++) acc[j][q] = 0.0f;
    cp_wait0();
    __syncthreads();

    // ---- layer 2: two 64-k stages ----
#pragma unroll 1
    for (int c = 0; c < 2; c++) {
        gemm_stage(sb, SA2, c * 128, e0, n0, lane, acc);
        __syncthreads();
        if (c == 0) {
            stage_w_async(sb, g_w2t_hi, g_w2t_lo, 128, 64, tid);
            cp_wait0();
            __syncthreads();
        }
    }

    // ---- epilogue 2: bias + elu + dot(W3), butterfly over tig ----
    float pa = 0.0f, pb = 0.0f;
#pragma unroll
    for (int nt = 0; nt < 8; nt++) {
        int nc = n0 + 8 * nt + 2 * tig;
        float w0 = w3s[nc], w1 = w3s[nc + 1];
        pa += elu1(acc[nt][0] + b2s[nc]) * w0 + elu1(acc[nt][1] + b2s[nc + 1]) * w1;
        pb += elu1(acc[nt][2] + b2s[nc]) * w0 + elu1(acc[nt][3] + b2s[nc + 1]) * w1;
    }
    pa += __shfl_xor_sync(0xffffffff, pa, 1);
    pa += __shfl_xor_sync(0xffffffff, pa, 2);
    pb += __shfl_xor_sync(0xffffffff, pb, 1);
    pb += __shfl_xor_sync(0xffffffff, pb, 2);
    float* red = (float*)(smem + (nw ? SM_R1 : SM_R0));
    if (tig == 0) {
        red[e0 + gid] = pa;
        red[e0 + gid + 8] = pb;
    }
    __syncthreads();
    if (tid < 64 && tid < nv) {
        float* r0 = (float*)(smem + SM_R0);
        float* r1 = (float*)(smem + SM_R1);
        out[tile + tid] = r0[tid] + r1[tid] + __ldg(b3);
    }
}

extern "C" void kernel_launch(void* const* d_in, const int* in_sizes, int n_in,
                              void* d_out, int out_size) {
    const float* x  = (const float*)d_in[0];
    const void*  ei = d_in[1];
    const float* W1 = (const float*)d_in[2];
    const float* b1 = (const float*)d_in[3];
    const float* W2 = (const float*)d_in[4];
    const float* b2 = (const float*)d_in[5];
    const float* W3 = (const float*)d_in[6];
    const float* b3 = (const float*)d_in[7];
    float* out = (float*)d_out;

    const int n_edges = out_size;
    const int n_nodes = in_sizes[0] / 128;

    cudaFuncSetAttribute(edge_mlp_hmma_kernel,
                         cudaFuncAttributeMaxDynamicSharedMemorySize, SMEM_BYTES);

    wconv_kernel<<<192, 256>>>(W1, W2);
    const int grid = (n_edges + EPT - 1) / EPT;
    edge_mlp_hmma_kernel<<<grid, THREADS, SMEM_BYTES>>>(x, ei, b1, b2, W3, b3,
                                                        out, n_edges, n_nodes);
}

// round 8
// speedup vs baseline: 1.2196x; 1.1438x over previous
#include <cuda_runtime.h>
#include <cuda_bf16.h>
#include <math.h>
#include <stdint.h>

// ---------------------------------------------------------------------------
// EdgeMLPMPN via mma.sync bf16x3-split (hi*hi + hi*lo + lo*hi, fp32 acc).
// R8 = R5 skeleton + x's bf16 hi/lo split precomputed ONCE into __device__
// globals, so the per-tile gather is pure cp.async (no LDG chain, no cvt/sub).
// EPT=64, 2 CTAs/SM, 8 warps (4m x 2n), 64k W stages via cp.async.
// ---------------------------------------------------------------------------

#define EPT 64
#define THREADS 256
#define NMAX 100000
#define SA1 528   // A1 row stride bytes (256 bf16 + pad); ldmatrix conflict-free
#define SA2 272   // h1 row stride (128 bf16 + pad)
#define SWS 144   // W chunk row stride (64 bf16 + pad)

#define SM_A_HI 0
#define SM_A_LO 33792                  // 64*528
#define SM_W_HI 67584
#define SM_W_LO (SM_W_HI + 18432)      // 128*144
#define SM_CTRL (SM_W_LO + 18432)      // 104448
#define SM_SIDS (SM_CTRL)              // 128 ints
#define SM_B1   (SM_CTRL + 512)
#define SM_B2   (SM_B1 + 512)
#define SM_W3   (SM_B2 + 512)
#define SM_R0   (SM_W3 + 512)
#define SM_R1   (SM_R0 + 256)
#define SMEM_BYTES (SM_R1 + 256)       // 104.5KB -> 2 CTAs/SM

__device__ __align__(16) __nv_bfloat16 g_x_hi[NMAX * 128];
__device__ __align__(16) __nv_bfloat16 g_x_lo[NMAX * 128];
__device__ __align__(16) __nv_bfloat16 g_w1t_hi[128 * 256];
__device__ __align__(16) __nv_bfloat16 g_w1t_lo[128 * 256];
__device__ __align__(16) __nv_bfloat16 g_w2t_hi[128 * 128];
__device__ __align__(16) __nv_bfloat16 g_w2t_lo[128 * 128];

__device__ __forceinline__ uint32_t smem_u32(const void* p) {
    uint32_t a;
    asm("{ .reg .u64 t; cvta.to.shared.u64 t, %1; cvt.u32.u64 %0, t; }" : "=r"(a) : "l"(p));
    return a;
}
__device__ __forceinline__ void ldm_x4(uint32_t addr, uint32_t r[4]) {
    asm volatile("ldmatrix.sync.aligned.m8n8.x4.shared.b16 {%0,%1,%2,%3}, [%4];"
                 : "=r"(r[0]), "=r"(r[1]), "=r"(r[2]), "=r"(r[3]) : "r"(addr));
}
__device__ __forceinline__ void hmma(float c[4], const uint32_t a[4],
                                     uint32_t b0, uint32_t b1) {
    asm volatile(
        "mma.sync.aligned.m16n8k16.row.col.f32.bf16.bf16.f32 "
        "{%0,%1,%2,%3}, {%4,%5,%6,%7}, {%8,%9}, {%0,%1,%2,%3};"
        : "+f"(c[0]), "+f"(c[1]), "+f"(c[2]), "+f"(c[3])
        : "r"(a[0]), "r"(a[1]), "r"(a[2]), "r"(a[3]), "r"(b0), "r"(b1));
}
__device__ __forceinline__ void cp16(uint32_t dst, const void* src) {
    asm volatile("cp.async.cg.shared.global [%0], [%1], 16;" :: "r"(dst), "l"(src));
}
__device__ __forceinline__ void cp_commit() {
    asm volatile("cp.async.commit_group;" ::: "memory");
}
__device__ __forceinline__ void cp_wait0() {
    asm volatile("cp.async.wait_group 0;" ::: "memory");
}
__device__ __forceinline__ float elu1(float v) { return v > 0.0f ? v : expm1f(v); }
__device__ __forceinline__ void split_bf16(float v, __nv_bfloat16& hi, __nv_bfloat16& lo) {
    hi = __float2bfloat16_rn(v);
    lo = __float2bfloat16_rn(v - __bfloat162float(hi));
}
union BF4 { __nv_bfloat16 b[4]; unsigned long long u; };
union BF2 { __nv_bfloat16 b[2]; uint32_t u; };

// ---------------- prologue A: split x into bf16 hi/lo ----------------
__global__ void xsplit_kernel(const float* __restrict__ x, int n4) {
    int i = blockIdx.x * blockDim.x + threadIdx.x;   // one float4 each
    if (i >= n4) return;
    float4 v = __ldg(reinterpret_cast<const float4*>(x) + i);
    BF4 h, l;
    split_bf16(v.x, h.b[0], l.b[0]);
    split_bf16(v.y, h.b[1], l.b[1]);
    split_bf16(v.z, h.b[2], l.b[2]);
    split_bf16(v.w, h.b[3], l.b[3]);
    *reinterpret_cast<unsigned long long*>(g_x_hi + i * 4) = h.u;
    *reinterpret_cast<unsigned long long*>(g_x_lo + i * 4) = l.u;
}

// ---------------- prologue B: transpose + bf16-split W1, W2 ----------------
__global__ void wconv_kernel(const float* __restrict__ W1, const float* __restrict__ W2) {
    int i = blockIdx.x * blockDim.x + threadIdx.x;
    if (i < 32768) {                     // W1T[n][k] <- W1[k][n]
        int n = i >> 8, k = i & 255;
        float v = __ldg(W1 + k * 128 + n);
        __nv_bfloat16 h, l; split_bf16(v, h, l);
        g_w1t_hi[i] = h; g_w1t_lo[i] = l;
    } else if (i < 49152) {              // W2T[n][k] <- W2[k][n]
        int j = i - 32768;
        int n = j >> 7, k = j & 127;
        float v = __ldg(W2 + k * 128 + n);
        __nv_bfloat16 h, l; split_bf16(v, h, l);
        g_w2t_hi[j] = h; g_w2t_lo[j] = l;
    }
}

// async-stage one [128 n][64 k] hi/lo W chunk
__device__ __forceinline__ void stage_w_async(uint32_t sb,
                                              const __nv_bfloat16* __restrict__ gh,
                                              const __nv_bfloat16* __restrict__ gl,
                                              int row_elems, int col0, int tid) {
#pragma unroll
    for (int it = 0; it < 4; it++) {
        int idx = tid + it * THREADS;
        int n = idx >> 3, j = idx & 7;
        cp16(sb + SM_W_HI + n * SWS + j * 16, gh + n * row_elems + col0 + j * 8);
        cp16(sb + SM_W_LO + n * SWS + j * 16, gl + n * row_elems + col0 + j * 8);
    }
    cp_commit();
}

// one 64-k stage (4 k-tiles); pass-major HMMA schedule over n-tile pairs
__device__ __forceinline__ void gemm_stage(uint32_t sb, int sa, int a_k0byte,
                                           int e0, int n0, int lane,
                                           float acc[8][4]) {
    const int rowA = lane & 15;
    const int chA = (lane >> 4) * 16;
    const int rowB = (lane & 7) + ((lane >> 4) << 3);
    const int chB = ((lane >> 3) & 1) * 16;

    uint32_t aH = sb + SM_A_HI + (e0 + rowA) * sa + chA + a_k0byte;
    uint32_t aL = sb + SM_A_LO + (e0 + rowA) * sa + chA + a_k0byte;
    uint32_t bH = sb + SM_W_HI + (n0 + rowB) * SWS + chB;
    uint32_t bL = sb + SM_W_LO + (n0 + rowB) * SWS + chB;

#pragma unroll
    for (int kt = 0; kt < 4; kt++) {
        uint32_t ah[4], al[4];
        ldm_x4(aH + kt * 32, ah);
        ldm_x4(aL + kt * 32, al);
#pragma unroll
        for (int g = 0; g < 2; g++) {
            uint32_t bh0[4], bh1[4], bl0[4], bl1[4];
            ldm_x4(bH + (2 * g + 0) * 16 * SWS + kt * 32, bh0);
            ldm_x4(bH + (2 * g + 1) * 16 * SWS + kt * 32, bh1);
            ldm_x4(bL + (2 * g + 0) * 16 * SWS + kt * 32, bl0);
            ldm_x4(bL + (2 * g + 1) * 16 * SWS + kt * 32, bl1);
            float (*a4)[4] = &acc[4 * g];
            hmma(a4[0], ah, bh0[0], bh0[1]);
            hmma(a4[1], ah, bh0[2], bh0[3]);
            hmma(a4[2], ah, bh1[0], bh1[1]);
            hmma(a4[3], ah, bh1[2], bh1[3]);
            hmma(a4[0], ah, bl0[0], bl0[1]);
            hmma(a4[1], ah, bl0[2], bl0[3]);
            hmma(a4[2], ah, bl1[0], bl1[1]);
            hmma(a4[3], ah, bl1[2], bl1[3]);
            hmma(a4[0], al, bh0[0], bh0[1]);
            hmma(a4[1], al, bh0[2], bh0[3]);
            hmma(a4[2], al, bh1[0], bh1[1]);
            hmma(a4[3], al, bh1[2], bh1[3]);
        }
    }
}

__global__ void __launch_bounds__(THREADS, 2)
edge_mlp_hmma_kernel(const void* __restrict__ ei,
                     const float* __restrict__ b1, const float* __restrict__ b2,
                     const float* __restrict__ W3, const float* __restrict__ b3,
                     float* __restrict__ out, int n_edges, int n_nodes) {
    extern __shared__ char smem[];
    const uint32_t sb = smem_u32(smem);
    const int tid = threadIdx.x, wid = tid >> 5, lane = tid & 31;
    const int gid = lane >> 2, tig = lane & 3;
    const int mw = wid >> 1, nw = wid & 1;
    const int e0 = mw * 16, n0 = nw * 64;
    const int tile = blockIdx.x * EPT;
    const int nv = min(EPT, n_edges - tile);

    // sniff edge_index dtype (int64 LE values < 2^31 => odd 32-bit words all 0)
    const int* ei32 = (const int*)ei;
    const long long* ei64 = (const long long*)ei;
    int odd_or = 0;
#pragma unroll
    for (int i = 1; i < 64; i += 2) odd_or |= ei32[i];
    const bool is64 = (odd_or == 0);

    int* sids = (int*)(smem + SM_SIDS);
    float* b1s = (float*)(smem + SM_B1);
    float* b2s = (float*)(smem + SM_B2);
    float* w3s = (float*)(smem + SM_W3);
    const int ncl = min(n_nodes, NMAX);
    if (tid < 128) {
        int half = tid >> 6, e = tid & 63;
        int ec = e < nv ? e : (nv - 1);
        int pos = half * n_edges + tile + ec;
        long long node = is64 ? ei64[pos] : (long long)ei32[pos];
        node = node < 0 ? 0 : (node >= ncl ? (long long)ncl - 1 : node);
        sids[tid] = (int)node;
        b1s[tid] = __ldg(b1 + tid);
        b2s[tid] = __ldg(b2 + tid);
        w3s[tid] = __ldg(W3 + tid);
    }
    __syncthreads();

    // ---- A tile staging: pure cp.async from precomputed g_x_hi/lo ----
    // chunk c: j (16B within 256B half-row), half, e
#pragma unroll
    for (int it = 0; it < 8; it++) {
        int c = tid + it * THREADS;        // 0..2047
        int j = c & 15, half = (c >> 4) & 1, e = c >> 5;
        int node = sids[half * 64 + e];
        int src = node * 128 + j * 8;
        uint32_t dst = e * SA1 + half * 256 + j * 16;
        cp16(sb + SM_A_HI + dst, g_x_hi + src);
        cp16(sb + SM_A_LO + dst, g_x_lo + src);
    }
    cp_commit();

    // prefetch W1 chunk 0 (own commit group)
    stage_w_async(sb, g_w1t_hi, g_w1t_lo, 256, 0, tid);

    cp_wait0();
    __syncthreads();

    float acc[8][4];
#pragma unroll
    for (int j = 0; j < 8; j++)
#pragma unroll
        for (int q = 0; q < 4; q++) acc[j][q] = 0.0f;

    // ---- layer 1: four 64-k stages ----
#pragma unroll 1
    for (int c = 0; c < 4; c++) {
        gemm_stage(sb, SA1, c * 128, e0, n0, lane, acc);
        __syncthreads();
        if (c < 3) {
            stage_w_async(sb, g_w1t_hi, g_w1t_lo, 256, (c + 1) * 64, tid);
            cp_wait0();
            __syncthreads();
        }
    }

    // prefetch W2 chunk 0; overlap with epilogue-1 resplit
    stage_w_async(sb, g_w2t_hi, g_w2t_lo, 128, 0, tid);

    // ---- epilogue 1: bias + elu, re-split h1 into A region (stride SA2) ----
#pragma unroll
    for (int nt = 0; nt < 8; nt++) {
        int nc = n0 + 8 * nt + 2 * tig;
        int ea = e0 + gid, eb = ea + 8;
        float v00 = elu1(acc[nt][0] + b1s[nc]);
        float v01 = elu1(acc[nt][1] + b1s[nc + 1]);
        float v10 = elu1(acc[nt][2] + b1s[nc]);
        float v11 = elu1(acc[nt][3] + b1s[nc + 1]);
        BF2 h, l;
        split_bf16(v00, h.b[0], l.b[0]);
        split_bf16(v01, h.b[1], l.b[1]);
        *reinterpret_cast<uint32_t*>(smem + SM_A_HI + ea * SA2 + nc * 2) = h.u;
        *reinterpret_cast<uint32_t*>(smem + SM_A_LO + ea * SA2 + nc * 2) = l.u;
        split_bf16(v10, h.b[0], l.b[0]);
        split_bf16(v11, h.b[1], l.b[1]);
        *reinterpret_cast<uint32_t*>(smem + SM_A_HI + eb * SA2 + nc * 2) = h.u;
        *reinterpret_cast<uint32_t*>(smem + SM_A_LO + eb * SA2 + nc * 2) = l.u;
    }
#pragma unroll
    for (int j = 0; j < 8; j++)
#pragma unroll
        for (int q = 0; q < 4; q++) acc[j][q] = 0.0f;
    cp_wait0();
    __syncthreads();

    // ---- layer 2: two 64-k stages ----
#pragma unroll 1
    for (int c = 0; c < 2; c++) {
        gemm_stage(sb, SA2, c * 128, e0, n0, lane, acc);
        __syncthreads();
        if (c == 0) {
            stage_w_async(sb, g_w2t_hi, g_w2t_lo, 128, 64, tid);
            cp_wait0();
            __syncthreads();
        }
    }

    // ---- epilogue 2: bias + elu + dot(W3), butterfly over tig ----
    float pa = 0.0f, pb = 0.0f;
#pragma unroll
    for (int nt = 0; nt < 8; nt++) {
        int nc = n0 + 8 * nt + 2 * tig;
        float w0 = w3s[nc], w1 = w3s[nc + 1];
        pa += elu1(acc[nt][0] + b2s[nc]) * w0 + elu1(acc[nt][1] + b2s[nc + 1]) * w1;
        pb += elu1(acc[nt][2] + b2s[nc]) * w0 + elu1(acc[nt][3] + b2s[nc + 1]) * w1;
    }
    pa += __shfl_xor_sync(0xffffffff, pa, 1);
    pa += __shfl_xor_sync(0xffffffff, pa, 2);
    pb += __shfl_xor_sync(0xffffffff, pb, 1);
    pb += __shfl_xor_sync(0xffffffff, pb, 2);
    float* red = (float*)(smem + (nw ? SM_R1 : SM_R0));
    if (tig == 0) {
        red[e0 + gid] = pa;
        red[e0 + gid + 8] = pb;
    }
    __syncthreads();
    if (tid < 64 && tid < nv) {
        float* r0 = (float*)(smem + SM_R0);
        float* r1 = (float*)(smem + SM_R1);
        out[tile + tid] = r0[tid] + r1[tid] + __ldg(b3);
    }
}

extern "C" void kernel_launch(void* const* d_in, const int* in_sizes, int n_in,
                              void* d_out, int out_size) {
    const float* x  = (const float*)d_in[0];
    const void*  ei = d_in[1];
    const float* W1 = (const float*)d_in[2];
    const float* b1 = (const float*)d_in[3];
    const float* W2 = (const float*)d_in[4];
    const float* b2 = (const float*)d_in[5];
    const float* W3 = (const float*)d_in[6];
    const float* b3 = (const float*)d_in[7];
    float* out = (float*)d_out;

    const int n_edges = out_size;
    const int n_nodes = in_sizes[0] / 128;
    const int n4 = (min(n_nodes, NMAX) * 128) / 4;

    cudaFuncSetAttribute(edge_mlp_hmma_kernel,
                         cudaFuncAttributeMaxDynamicSharedMemorySize, SMEM_BYTES);

    wconv_kernel<<<192, 256>>>(W1, W2);
    xsplit_kernel<<<(n4 + 255) / 256, 256>>>(x, n4);
    const int grid = (n_edges + EPT - 1) / EPT;
    edge_mlp_hmma_kernel<<<grid, THREADS, SMEM_BYTES>>>(ei, b1, b2, W3, b3,
                                                        out, n_edges, n_nodes);
}